// round 14
// baseline (speedup 1.0000x reference)
#include <cuda_runtime.h>
#include <cuda_bf16.h>
#include <math.h>
#include <cstdint>

#define BATCH 8
#define SEQ   2048
#define DIM   128
#define QBM   64            // qkv token tile
#define ABM   64            // attention q rows per CTA
#define ABN   64            // keys per iteration
#define NQT   (SEQ / ABM)   // 32

// SMEM byte offsets (attention kernel)
#define SQH 0               // Q hi  [64][136] bf16 (272B rows)
#define SQL 17408           // Q lo
#define SKH 34816           // K hi  [64][136]
#define SKL 52224           // K lo
#define SVH 69632           // V^T hi [128][72] (144B rows)
#define SVL 88064           // V^T lo
#define SMEM_ATTN 106496

// Scratch (device globals — no allocation allowed)
__device__ __nv_bfloat16 g_qh[BATCH * SEQ * DIM];
__device__ __nv_bfloat16 g_ql[BATCH * SEQ * DIM];
__device__ __nv_bfloat16 g_kh[BATCH * SEQ * DIM];
__device__ __nv_bfloat16 g_kl[BATCH * SEQ * DIM];
__device__ __nv_bfloat16 g_vth[BATCH * DIM * SEQ];   // [b][d][t]
__device__ __nv_bfloat16 g_vtl[BATCH * DIM * SEQ];

__device__ __forceinline__ uint32_t smem_u32(const void* p) {
    uint32_t a;
    asm("{ .reg .u64 t; cvta.to.shared.u64 t, %1; cvt.u32.u64 %0, t; }" : "=r"(a) : "l"(p));
    return a;
}
__device__ __forceinline__ float ex2f(float x) {
    float r; asm("ex2.approx.ftz.f32 %0, %1;" : "=f"(r) : "f"(x)); return r;
}

#define LDSM4(r0, r1, r2, r3, addr) \
    asm volatile("ldmatrix.sync.aligned.m8n8.x4.shared.b16 {%0,%1,%2,%3}, [%4];" \
        : "=r"(r0), "=r"(r1), "=r"(r2), "=r"(r3) : "r"(addr))
#define MMA16816(c, a0, a1, a2, a3, b0, b1) \
    asm volatile("mma.sync.aligned.m16n8k16.row.col.f32.bf16.bf16.f32 " \
        "{%0,%1,%2,%3}, {%4,%5,%6,%7}, {%8,%9}, {%0,%1,%2,%3};" \
        : "+f"((c)[0]), "+f"((c)[1]), "+f"((c)[2]), "+f"((c)[3]) \
        : "r"(a0), "r"(a1), "r"(a2), "r"(a3), "r"(b0), "r"(b1))

// split fp32 pair into bf16x2 hi + bf16x2 lo
__device__ __forceinline__ void hilo2(float x, float y, uint32_t& h, uint32_t& l) {
    __nv_bfloat162 hp = __float22bfloat162_rn(make_float2(x, y));
    float2 hf = __bfloat1622float2(hp);
    __nv_bfloat162 lp = __float22bfloat162_rn(make_float2(x - hf.x, y - hf.y));
    h = *(uint32_t*)&hp;
    l = *(uint32_t*)&lp;
}
__device__ __forceinline__ void split4(float4 a, uint2& h, uint2& l) {
    uint32_t h0, l0, h1, l1;
    hilo2(a.x, a.y, h0, l0);
    hilo2(a.z, a.w, h1, l1);
    h.x = h0; h.y = h1; l.x = l0; l.y = l1;
}
__device__ __forceinline__ void st4_as_2x2(float* p, float4 v) {
    *(float2*)(p)     = make_float2(v.x, v.y);
    *(float2*)(p + 2) = make_float2(v.z, v.w);
}

// ---------------------------------------------------------------------------
// QKV projection + bf16 hi/lo split outputs. grid (32, 8, 3), block 256.
// ---------------------------------------------------------------------------
__global__ __launch_bounds__(256, 1)
void qkv_kernel(const float* __restrict__ x, const float* __restrict__ Wk,
                const float* __restrict__ Wq, const float* __restrict__ Wv) {
    extern __shared__ float sm[];
    float* sWt = sm;               // [128][128] W^T
    float* sX  = sm + DIM * DIM;   // [64][128]

    const int tq = blockIdx.x, b = blockIdx.y, which = blockIdx.z;
    const float* W = (which == 0) ? Wq : (which == 1) ? Wk : Wv;
    const int tid = threadIdx.x;

    {   // W transposed into SMEM
        int d = tid >> 1, c0 = (tid & 1) * 64;
        const float4* src = (const float4*)(W + d * DIM + c0);
        #pragma unroll
        for (int i = 0; i < 16; i++) {
            float4 w = src[i]; int c = c0 + i * 4;
            sWt[(c + 0) * DIM + d] = w.x; sWt[(c + 1) * DIM + d] = w.y;
            sWt[(c + 2) * DIM + d] = w.z; sWt[(c + 3) * DIM + d] = w.w;
        }
    }
    {   // x tile
        const float4* src = (const float4*)(x + ((size_t)b * SEQ + tq * QBM) * DIM);
        float4* dst = (float4*)sX;
        #pragma unroll
        for (int i = 0; i < 8; i++) dst[tid + i * 256] = src[tid + i * 256];
    }
    __syncthreads();

    const int cx = tid & 31, ry = tid >> 5;
    float acc[8][4];
    #pragma unroll
    for (int i = 0; i < 8; i++)
        #pragma unroll
        for (int j = 0; j < 4; j++) acc[i][j] = 0.f;

    #pragma unroll 4
    for (int c = 0; c < DIM; c++) {
        float4 w = *(const float4*)(sWt + c * DIM + cx * 4);
        #pragma unroll
        for (int i = 0; i < 8; i++) {
            float xv = sX[(ry * 8 + i) * DIM + c];
            acc[i][0] += xv * w.x; acc[i][1] += xv * w.y;
            acc[i][2] += xv * w.z; acc[i][3] += xv * w.w;
        }
    }

    if (which == 0) {   // Q: pre-scale by log2e/sqrt(128), split
        const float QS = 0.08838834764831845f * 1.4426950408889634f;
        size_t rowbase = (size_t)b * SEQ + tq * QBM;
        #pragma unroll
        for (int i = 0; i < 8; i++) {
            size_t g = (rowbase + ry * 8 + i) * DIM + cx * 4;
            float4 a = make_float4(acc[i][0]*QS, acc[i][1]*QS, acc[i][2]*QS, acc[i][3]*QS);
            uint2 h, l; split4(a, h, l);
            *(uint2*)(g_qh + g) = h; *(uint2*)(g_ql + g) = l;
        }
    } else if (which == 1) {   // K: split
        size_t rowbase = (size_t)b * SEQ + tq * QBM;
        #pragma unroll
        for (int i = 0; i < 8; i++) {
            size_t g = (rowbase + ry * 8 + i) * DIM + cx * 4;
            float4 a = make_float4(acc[i][0], acc[i][1], acc[i][2], acc[i][3]);
            uint2 h, l; split4(a, h, l);
            *(uint2*)(g_kh + g) = h; *(uint2*)(g_kl + g) = l;
        }
    } else {   // V: transpose via SMEM stage, split
        __syncthreads();
        float* sOut = sm;   // [64][130]
        #pragma unroll
        for (int i = 0; i < 8; i++)
            st4_as_2x2(sOut + (ry * 8 + i) * 130 + cx * 4,
                       make_float4(acc[i][0], acc[i][1], acc[i][2], acc[i][3]));
        __syncthreads();
        int dr = tid >> 1, t0 = (tid & 1) * 32;
        size_t gb = ((size_t)b * DIM + dr) * SEQ + tq * QBM + t0;
        #pragma unroll
        for (int k4 = 0; k4 < 8; k4++) {
            float4 v = make_float4(sOut[(t0 + k4*4 + 0) * 130 + dr],
                                   sOut[(t0 + k4*4 + 1) * 130 + dr],
                                   sOut[(t0 + k4*4 + 2) * 130 + dr],
                                   sOut[(t0 + k4*4 + 3) * 130 + dr]);
            uint2 h, l; split4(v, h, l);
            *(uint2*)(g_vth + gb + k4*4) = h;
            *(uint2*)(g_vtl + gb + k4*4) = l;
        }
    }
}

// ---------------------------------------------------------------------------
// Warp-MMA flash attention, fixed-offset softmax, bf16 2-term x 3 passes.
// 128 threads (4 warps x m16), BM=64 rows/CTA, BN=64 keys/iter, 2 CTAs/SM.
// Exact pairing: SMs 0-107 get qt pairs summing to 26; SMs 108-147 get
// heavy singles qt 27-31 (classic placement: SM = LUT[bid % 148]).
// ---------------------------------------------------------------------------
__global__ __launch_bounds__(128, 2)
void attn_kernel(float* __restrict__ out) {
    extern __shared__ char smem[];
    const uint32_t sb = smem_u32(smem);
    const int tid = threadIdx.x, wid = tid >> 5, lane = tid & 31;

    // ---- work mapping (see header comment) ----
    int qt, b;
    {
        const int bid = blockIdx.x;
        if (bid >= 108 && bid < 148) {           // singles: heavy tiles
            int p = bid - 108;
            qt = 27 + (p >> 3); b = p & 7;
        } else if (bid < 108) {                  // first of pair
            if (bid < 104) { qt = bid >> 3; b = bid & 7; }
            else           { qt = 13; b = (bid - 104) * 2; }
        } else {                                 // second of pair (bid >= 148)
            int p = bid - 148;
            if (p < 104) { qt = 26 - (p >> 3); b = p & 7; }
            else         { qt = 13; b = (p - 104) * 2 + 1; }
        }
    }
    const int qbase = qt * ABM;
    const int m0 = wid * 16;
    const int g  = lane >> 2;            // fragment row within 8
    const int q2 = (lane & 3) * 2;       // fragment col pair
    const int nk = qt + 1;               // 64-key tiles to process

    // ---- load Q tile (hi/lo) into SMEM [64][136] ----
    {
        const __nv_bfloat16* qh = g_qh + ((size_t)b * SEQ + qbase) * DIM;
        const __nv_bfloat16* ql = g_ql + ((size_t)b * SEQ + qbase) * DIM;
        #pragma unroll
        for (int j = 0; j < 8; j++) {
            int i = tid + j * 128;
            int r = i >> 4, cs = i & 15;
            *(uint4*)(smem + SQH + r * 272 + cs * 16) = *(const uint4*)(qh + r * DIM + cs * 8);
            *(uint4*)(smem + SQL + r * 272 + cs * 16) = *(const uint4*)(ql + r * DIM + cs * 8);
        }
    }

    // ldmatrix per-lane base addresses
    const int aRow = m0 + (lane & 7) + ((lane >> 3) & 1) * 8;
    const int aCol = ((lane >> 4) & 1) * 16;
    const uint32_t aQH = sb + SQH + aRow * 272 + aCol;
    const uint32_t aQL = sb + SQL + aRow * 272 + aCol;
    // x4 B-operand addressing: lanes 0-15 -> tile nt (k lo/hi), 16-31 -> nt+1
    const int bRow4 = (lane & 7) + ((lane >> 4) & 1) * 8;
    const int bCol4 = ((lane >> 3) & 1) * 16;
    const uint32_t bKH = sb + SKH + bRow4 * 272 + bCol4;
    const uint32_t bKL = sb + SKL + bRow4 * 272 + bCol4;
    const uint32_t bVH = sb + SVH + bRow4 * 144 + bCol4;
    const uint32_t bVL = sb + SVL + bRow4 * 144 + bCol4;

    float o[16][4];
    #pragma unroll
    for (int nt = 0; nt < 16; nt++)
        #pragma unroll
        for (int j = 0; j < 4; j++) o[nt][j] = 0.f;
    float ls0 = 0.f, ls1 = 0.f;

    const __nv_bfloat16* Kh = g_kh + (size_t)b * SEQ * DIM;
    const __nv_bfloat16* Kl = g_kl + (size_t)b * SEQ * DIM;
    const __nv_bfloat16* Vh = g_vth + (size_t)b * DIM * SEQ;
    const __nv_bfloat16* Vl = g_vtl + (size_t)b * DIM * SEQ;

    for (int kt = 0; kt < nk; kt++) {
        const int kb = kt * ABN;
        __syncthreads();
        // K tiles [64][128] -> [64][136]
        #pragma unroll
        for (int j = 0; j < 8; j++) {
            int i = tid + j * 128;
            int r = i >> 4, cs = i & 15;
            *(uint4*)(smem + SKH + r * 272 + cs * 16) =
                *(const uint4*)(Kh + (size_t)(kb + r) * DIM + cs * 8);
            *(uint4*)(smem + SKL + r * 272 + cs * 16) =
                *(const uint4*)(Kl + (size_t)(kb + r) * DIM + cs * 8);
        }
        // V^T tiles [128][64] -> [128][72]
        #pragma unroll
        for (int j = 0; j < 8; j++) {
            int i = tid + j * 128;
            int d = i >> 3, cs = i & 7;
            *(uint4*)(smem + SVH + d * 144 + cs * 16) =
                *(const uint4*)(Vh + (size_t)d * SEQ + kb + cs * 8);
            *(uint4*)(smem + SVL + d * 144 + cs * 16) =
                *(const uint4*)(Vl + (size_t)d * SEQ + kb + cs * 8);
        }
        __syncthreads();

        // ---- S = Q K^T (3 passes fused per k-step; x4 B loads per nt-pair) ----
        float s[8][4];
        #pragma unroll
        for (int nt = 0; nt < 8; nt++)
            #pragma unroll
            for (int j = 0; j < 4; j++) s[nt][j] = 0.f;

        #pragma unroll
        for (int k8 = 0; k8 < 8; k8++) {
            uint32_t ah[4], al[4];
            LDSM4(ah[0], ah[1], ah[2], ah[3], aQH + k8 * 32);
            LDSM4(al[0], al[1], al[2], al[3], aQL + k8 * 32);
            #pragma unroll
            for (int np = 0; np < 4; np++) {
                uint32_t bh[4], bl[4];
                LDSM4(bh[0], bh[1], bh[2], bh[3], bKH + np * 4352 + k8 * 32);
                LDSM4(bl[0], bl[1], bl[2], bl[3], bKL + np * 4352 + k8 * 32);
                MMA16816(s[2*np],   ah[0], ah[1], ah[2], ah[3], bh[0], bh[1]);
                MMA16816(s[2*np],   ah[0], ah[1], ah[2], ah[3], bl[0], bl[1]);
                MMA16816(s[2*np],   al[0], al[1], al[2], al[3], bh[0], bh[1]);
                MMA16816(s[2*np+1], ah[0], ah[1], ah[2], ah[3], bh[2], bh[3]);
                MMA16816(s[2*np+1], ah[0], ah[1], ah[2], ah[3], bl[2], bl[3]);
                MMA16816(s[2*np+1], al[0], al[1], al[2], al[3], bh[2], bh[3]);
            }
        }

        // ---- mask + exp2(s - 17.3125) + lsum ----
        const float OFF = 17.3125f;
        const bool nm = (kb + ABN - 1) > (qbase + m0);
        const int r0 = qbase + m0 + g, r1 = r0 + 8;
        #pragma unroll
        for (int nt = 0; nt < 8; nt++) {
            if (nm) {
                int c0 = kb + nt * 8 + q2;
                s[nt][0] = (c0     <= r0) ? ex2f(s[nt][0] - OFF) : 0.f;
                s[nt][1] = (c0 + 1 <= r0) ? ex2f(s[nt][1] - OFF) : 0.f;
                s[nt][2] = (c0     <= r1) ? ex2f(s[nt][2] - OFF) : 0.f;
                s[nt][3] = (c0 + 1 <= r1) ? ex2f(s[nt][3] - OFF) : 0.f;
            } else {
                s[nt][0] = ex2f(s[nt][0] - OFF);
                s[nt][1] = ex2f(s[nt][1] - OFF);
                s[nt][2] = ex2f(s[nt][2] - OFF);
                s[nt][3] = ex2f(s[nt][3] - OFF);
            }
            ls0 += s[nt][0] + s[nt][1];
            ls1 += s[nt][2] + s[nt][3];
        }

        // ---- repack P C-frags -> A-frags (hi/lo) ----
        uint32_t ph[4][4], pl[4][4];
        #pragma unroll
        for (int kk = 0; kk < 4; kk++) {
            int n0 = 2 * kk, n1 = 2 * kk + 1;
            hilo2(s[n0][0], s[n0][1], ph[kk][0], pl[kk][0]);
            hilo2(s[n0][2], s[n0][3], ph[kk][1], pl[kk][1]);
            hilo2(s[n1][0], s[n1][1], ph[kk][2], pl[kk][2]);
            hilo2(s[n1][2], s[n1][3], ph[kk][3], pl[kk][3]);
        }

        // ---- O += P V (3 passes; x4 V loads per nt-pair) ----
        #pragma unroll
        for (int kk = 0; kk < 4; kk++) {
            #pragma unroll
            for (int np = 0; np < 8; np++) {
                uint32_t vh[4], vl[4];
                LDSM4(vh[0], vh[1], vh[2], vh[3], bVH + np * 2304 + kk * 32);
                LDSM4(vl[0], vl[1], vl[2], vl[3], bVL + np * 2304 + kk * 32);
                MMA16816(o[2*np],   ph[kk][0], ph[kk][1], ph[kk][2], ph[kk][3], vh[0], vh[1]);
                MMA16816(o[2*np],   ph[kk][0], ph[kk][1], ph[kk][2], ph[kk][3], vl[0], vl[1]);
                MMA16816(o[2*np],   pl[kk][0], pl[kk][1], pl[kk][2], pl[kk][3], vh[0], vh[1]);
                MMA16816(o[2*np+1], ph[kk][0], ph[kk][1], ph[kk][2], ph[kk][3], vh[2], vh[3]);
                MMA16816(o[2*np+1], ph[kk][0], ph[kk][1], ph[kk][2], ph[kk][3], vl[2], vl[3]);
                MMA16816(o[2*np+1], pl[kk][0], pl[kk][1], pl[kk][2], pl[kk][3], vh[2], vh[3]);
            }
        }
    }

    // ---- epilogue: quad-reduce lsum, normalize, store ----
    ls0 += __shfl_xor_sync(0xffffffffu, ls0, 1);
    ls0 += __shfl_xor_sync(0xffffffffu, ls0, 2);
    ls1 += __shfl_xor_sync(0xffffffffu, ls1, 1);
    ls1 += __shfl_xor_sync(0xffffffffu, ls1, 2);
    const float inv0 = 1.0f / ls0, inv1 = 1.0f / ls1;
    float* op = out + ((size_t)b * SEQ + qbase + m0) * DIM;
    #pragma unroll
    for (int nt = 0; nt < 16; nt++) {
        *(float2*)(op + (size_t)g * DIM + nt * 8 + q2) =
            make_float2(o[nt][0] * inv0, o[nt][1] * inv0);
        *(float2*)(op + (size_t)(g + 8) * DIM + nt * 8 + q2) =
            make_float2(o[nt][2] * inv1, o[nt][3] * inv1);
    }
}

// ---------------------------------------------------------------------------
extern "C" void kernel_launch(void* const* d_in, const int* in_sizes, int n_in,
                              void* d_out, int out_size) {
    const float* x  = (const float*)d_in[0];
    const float* Wk = (const float*)d_in[1];
    const float* Wq = (const float*)d_in[2];
    const float* Wv = (const float*)d_in[3];
    float* out = (float*)d_out;

    const size_t qkv_smem = (size_t)(DIM * DIM + QBM * DIM) * sizeof(float);  // 98304

    cudaFuncSetAttribute(qkv_kernel,  cudaFuncAttributeMaxDynamicSharedMemorySize, (int)qkv_smem);
    cudaFuncSetAttribute(attn_kernel, cudaFuncAttributeMaxDynamicSharedMemorySize, SMEM_ATTN);

    dim3 qkv_grid(SEQ / QBM, BATCH, 3);
    qkv_kernel<<<qkv_grid, 256, qkv_smem>>>(x, Wk, Wq, Wv);

    attn_kernel<<<NQT * BATCH, 128, SMEM_ATTN>>>(out);
}

// round 15
// speedup vs baseline: 1.3744x; 1.3744x over previous
#include <cuda_runtime.h>
#include <cuda_bf16.h>
#include <math.h>
#include <cstdint>

#define BATCH 8
#define SEQ   2048
#define DIM   128
#define QBM   64            // qkv token tile
#define ABM   64            // attention q rows per CTA
#define ABN   64            // keys per iteration
#define NQT   (SEQ / ABM)   // 32

// Attention SMEM byte offsets (all tiles [64][136] bf16, 272B rows)
#define SQH 0
#define SQL 17408
#define SKH 34816
#define SKL 52224
#define SVH 69632
#define SVL 87040
#define SMEM_ATTN 104448

// QKV SMEM: W hi/lo [128][136], x hi/lo [64][136]
#define SWH 0
#define SWL 34816
#define SXH 69632
#define SXL 87040
#define SMEM_QKV 104448

// Scratch (device globals — no allocation allowed)
__device__ __nv_bfloat16 g_qh[BATCH * SEQ * DIM];
__device__ __nv_bfloat16 g_ql[BATCH * SEQ * DIM];
__device__ __nv_bfloat16 g_kh[BATCH * SEQ * DIM];
__device__ __nv_bfloat16 g_kl[BATCH * SEQ * DIM];
__device__ __nv_bfloat16 g_vh[BATCH * SEQ * DIM];   // natural [b][t][d]
__device__ __nv_bfloat16 g_vl[BATCH * SEQ * DIM];

__device__ __forceinline__ uint32_t smem_u32(const void* p) {
    uint32_t a;
    asm("{ .reg .u64 t; cvta.to.shared.u64 t, %1; cvt.u32.u64 %0, t; }" : "=r"(a) : "l"(p));
    return a;
}
__device__ __forceinline__ float ex2f(float x) {
    float r; asm("ex2.approx.ftz.f32 %0, %1;" : "=f"(r) : "f"(x)); return r;
}

#define LDSM4(r0, r1, r2, r3, addr) \
    asm volatile("ldmatrix.sync.aligned.m8n8.x4.shared.b16 {%0,%1,%2,%3}, [%4];" \
        : "=r"(r0), "=r"(r1), "=r"(r2), "=r"(r3) : "r"(addr))
#define LDSM4T(r0, r1, r2, r3, addr) \
    asm volatile("ldmatrix.sync.aligned.m8n8.x4.trans.shared.b16 {%0,%1,%2,%3}, [%4];" \
        : "=r"(r0), "=r"(r1), "=r"(r2), "=r"(r3) : "r"(addr))
#define MMA16816(c, a0, a1, a2, a3, b0, b1) \
    asm volatile("mma.sync.aligned.m16n8k16.row.col.f32.bf16.bf16.f32 " \
        "{%0,%1,%2,%3}, {%4,%5,%6,%7}, {%8,%9}, {%0,%1,%2,%3};" \
        : "+f"((c)[0]), "+f"((c)[1]), "+f"((c)[2]), "+f"((c)[3]) \
        : "r"(a0), "r"(a1), "r"(a2), "r"(a3), "r"(b0), "r"(b1))

// split fp32 pair into bf16x2 hi + bf16x2 lo
__device__ __forceinline__ void hilo2(float x, float y, uint32_t& h, uint32_t& l) {
    __nv_bfloat162 hp = __float22bfloat162_rn(make_float2(x, y));
    float2 hf = __bfloat1622float2(hp);
    __nv_bfloat162 lp = __float22bfloat162_rn(make_float2(x - hf.x, y - hf.y));
    h = *(uint32_t*)&hp;
    l = *(uint32_t*)&lp;
}
__device__ __forceinline__ void split4(float4 a, uint2& h, uint2& l) {
    uint32_t h0, l0, h1, l1;
    hilo2(a.x, a.y, h0, l0);
    hilo2(a.z, a.w, h1, l1);
    h.x = h0; h.y = h1; l.x = l0; l.y = l1;
}

// ---------------------------------------------------------------------------
// QKV projection via warp-MMA (3-pass bf16 hi/lo), outputs hi/lo bf16.
// grid (32, 8, 3), 128 threads (4 warps x m16). y[t][d] = sum_c x[t][c] W[d][c]
// ---------------------------------------------------------------------------
__global__ __launch_bounds__(128, 2)
void qkv_kernel(const float* __restrict__ x, const float* __restrict__ Wk,
                const float* __restrict__ Wq, const float* __restrict__ Wv) {
    extern __shared__ char smem[];
    const uint32_t sb = smem_u32(smem);
    const int tid = threadIdx.x, wid = tid >> 5, lane = tid & 31;
    const int tq = blockIdx.x, b = blockIdx.y, which = blockIdx.z;
    const float* W = (which == 0) ? Wq : (which == 1) ? Wk : Wv;

    // W [128][128] f32 -> split hi/lo into smem [128][136]
    #pragma unroll
    for (int j = 0; j < 32; j++) {
        int i = tid + j * 128;
        int r = i >> 5, c4 = (i & 31) * 4;
        float4 w = *(const float4*)(W + r * DIM + c4);
        uint2 h, l; split4(w, h, l);
        *(uint2*)(smem + SWH + r * 272 + c4 * 2) = h;
        *(uint2*)(smem + SWL + r * 272 + c4 * 2) = l;
    }
    // x tile [64][128] f32 (Q pre-scaled) -> split hi/lo
    const float sc = (which == 0) ? (0.08838834764831845f * 1.4426950408889634f) : 1.0f;
    #pragma unroll
    for (int j = 0; j < 16; j++) {
        int i = tid + j * 128;
        int r = i >> 5, c4 = (i & 31) * 4;
        float4 v = *(const float4*)(x + ((size_t)b * SEQ + tq * QBM + r) * DIM + c4);
        v.x *= sc; v.y *= sc; v.z *= sc; v.w *= sc;
        uint2 h, l; split4(v, h, l);
        *(uint2*)(smem + SXH + r * 272 + c4 * 2) = h;
        *(uint2*)(smem + SXL + r * 272 + c4 * 2) = l;
    }
    __syncthreads();

    const int m0 = wid * 16;
    const int g  = lane >> 2, q2 = (lane & 3) * 2;
    const int aRow = m0 + (lane & 7) + ((lane >> 3) & 1) * 8;
    const int aCol = ((lane >> 4) & 1) * 16;
    const uint32_t aXH = sb + SXH + aRow * 272 + aCol;
    const uint32_t aXL = sb + SXL + aRow * 272 + aCol;
    const int bRow4 = (lane & 7) + ((lane >> 4) & 1) * 8;
    const int bCol4 = ((lane >> 3) & 1) * 16;
    const uint32_t bWH = sb + SWH + bRow4 * 272 + bCol4;
    const uint32_t bWL = sb + SWL + bRow4 * 272 + bCol4;

    float c[16][4];
    #pragma unroll
    for (int nt = 0; nt < 16; nt++)
        #pragma unroll
        for (int j = 0; j < 4; j++) c[nt][j] = 0.f;

    #pragma unroll
    for (int k8 = 0; k8 < 8; k8++) {
        uint32_t ah[4], al[4];
        LDSM4(ah[0], ah[1], ah[2], ah[3], aXH + k8 * 32);
        LDSM4(al[0], al[1], al[2], al[3], aXL + k8 * 32);
        #pragma unroll
        for (int np = 0; np < 8; np++) {
            uint32_t bh[4], bl[4];
            LDSM4(bh[0], bh[1], bh[2], bh[3], bWH + np * 4352 + k8 * 32);
            LDSM4(bl[0], bl[1], bl[2], bl[3], bWL + np * 4352 + k8 * 32);
            MMA16816(c[2*np],   ah[0], ah[1], ah[2], ah[3], bh[0], bh[1]);
            MMA16816(c[2*np],   ah[0], ah[1], ah[2], ah[3], bl[0], bl[1]);
            MMA16816(c[2*np],   al[0], al[1], al[2], al[3], bh[0], bh[1]);
            MMA16816(c[2*np+1], ah[0], ah[1], ah[2], ah[3], bh[2], bh[3]);
            MMA16816(c[2*np+1], ah[0], ah[1], ah[2], ah[3], bl[2], bl[3]);
            MMA16816(c[2*np+1], al[0], al[1], al[2], al[3], bh[2], bh[3]);
        }
    }

    __nv_bfloat16* oh = (which == 0) ? g_qh : (which == 1) ? g_kh : g_vh;
    __nv_bfloat16* ol = (which == 0) ? g_ql : (which == 1) ? g_kl : g_vl;
    const size_t r0 = (size_t)b * SEQ + tq * QBM + m0 + g;
    #pragma unroll
    for (int nt = 0; nt < 16; nt++) {
        uint32_t h, l;
        hilo2(c[nt][0], c[nt][1], h, l);
        *(uint32_t*)(oh + r0 * DIM + nt * 8 + q2) = h;
        *(uint32_t*)(ol + r0 * DIM + nt * 8 + q2) = l;
        hilo2(c[nt][2], c[nt][3], h, l);
        *(uint32_t*)(oh + (r0 + 8) * DIM + nt * 8 + q2) = h;
        *(uint32_t*)(ol + (r0 + 8) * DIM + nt * 8 + q2) = l;
    }
}

// ---------------------------------------------------------------------------
// Warp-MMA flash attention, fixed-offset softmax, bf16 2-term x 3 passes.
// 128 threads (4 warps x m16), BM=64, BN=64, 2 CTAs/SM, x4 ldmatrix.
// V natural [t][d], PV B-frags via ldmatrix.trans.
// Schedule: singles (SMs 108-147) get qt 22-26; pairs: (31..27 with 0..4),
// (21..14 with 5..12), (13,13). Placement assumption: SM = LUT[bid % 148].
// ---------------------------------------------------------------------------
__global__ __launch_bounds__(128, 2)
void attn_kernel(float* __restrict__ out) {
    extern __shared__ char smem[];
    const uint32_t sb = smem_u32(smem);
    const int tid = threadIdx.x, wid = tid >> 5, lane = tid & 31;

    // ---- work mapping ----
    int qt, b;
    {
        const int bid = blockIdx.x;
        if (bid >= 108 && bid < 148) {                 // singles: mid tiles
            int p = bid - 108;
            qt = 22 + (p >> 3); b = p & 7;
        } else {
            const int i = (bid < 108) ? bid : bid - 148;
            const bool first = (bid < 108);
            if (i < 40)       { qt = first ? 31 - (i >> 3) : (i >> 3);            b = i & 7; }
            else if (i < 104) { int j = i - 40;
                                qt = first ? 21 - (j >> 3) : 5 + (j >> 3);        b = i & 7; }
            else              { int m = i - 104; qt = 13; b = 2 * m + (first ? 0 : 1); }
        }
    }
    const int qbase = qt * ABM;
    const int m0 = wid * 16;
    const int g  = lane >> 2;
    const int q2 = (lane & 3) * 2;
    const int nk = qt + 1;

    // ---- load Q tile (hi/lo) into SMEM [64][136] ----
    {
        const __nv_bfloat16* qh = g_qh + ((size_t)b * SEQ + qbase) * DIM;
        const __nv_bfloat16* ql = g_ql + ((size_t)b * SEQ + qbase) * DIM;
        #pragma unroll
        for (int j = 0; j < 8; j++) {
            int i = tid + j * 128;
            int r = i >> 4, cs = i & 15;
            *(uint4*)(smem + SQH + r * 272 + cs * 16) = *(const uint4*)(qh + r * DIM + cs * 8);
            *(uint4*)(smem + SQL + r * 272 + cs * 16) = *(const uint4*)(ql + r * DIM + cs * 8);
        }
    }

    // ldmatrix per-lane base addresses
    const int aRow = m0 + (lane & 7) + ((lane >> 3) & 1) * 8;
    const int aCol = ((lane >> 4) & 1) * 16;
    const uint32_t aQH = sb + SQH + aRow * 272 + aCol;
    const uint32_t aQL = sb + SQL + aRow * 272 + aCol;
    // K (non-trans x4): lanes 0-15 -> tile np (k lo/hi), 16-31 -> np+1
    const int bRow4 = (lane & 7) + ((lane >> 4) & 1) * 8;
    const int bCol4 = ((lane >> 3) & 1) * 16;
    const uint32_t bKH = sb + SKH + bRow4 * 272 + bCol4;
    const uint32_t bKL = sb + SKL + bRow4 * 272 + bCol4;
    // V (trans x4): lanes 0-7 -> t0-7, 8-15 -> t8-15 (d-blk lo); 16-31 -> d-blk hi
    const int vRow = (lane & 7) + ((lane >> 3) & 1) * 8;
    const int vCol = ((lane >> 4) & 1) * 16;
    const uint32_t bVH = sb + SVH + vRow * 272 + vCol;
    const uint32_t bVL = sb + SVL + vRow * 272 + vCol;

    float o[16][4];
    #pragma unroll
    for (int nt = 0; nt < 16; nt++)
        #pragma unroll
        for (int j = 0; j < 4; j++) o[nt][j] = 0.f;
    float ls0 = 0.f, ls1 = 0.f;

    const __nv_bfloat16* Kh = g_kh + (size_t)b * SEQ * DIM;
    const __nv_bfloat16* Kl = g_kl + (size_t)b * SEQ * DIM;
    const __nv_bfloat16* Vh = g_vh + (size_t)b * SEQ * DIM;
    const __nv_bfloat16* Vl = g_vl + (size_t)b * SEQ * DIM;

    for (int kt = 0; kt < nk; kt++) {
        const int kb = kt * ABN;
        __syncthreads();
        // K + V tiles [64][128] -> [64][136]
        #pragma unroll
        for (int j = 0; j < 8; j++) {
            int i = tid + j * 128;
            int r = i >> 4, cs = i & 15;
            size_t gidx = (size_t)(kb + r) * DIM + cs * 8;
            *(uint4*)(smem + SKH + r * 272 + cs * 16) = *(const uint4*)(Kh + gidx);
            *(uint4*)(smem + SKL + r * 272 + cs * 16) = *(const uint4*)(Kl + gidx);
            *(uint4*)(smem + SVH + r * 272 + cs * 16) = *(const uint4*)(Vh + gidx);
            *(uint4*)(smem + SVL + r * 272 + cs * 16) = *(const uint4*)(Vl + gidx);
        }
        __syncthreads();

        // ---- S = Q K^T ----
        float s[8][4];
        #pragma unroll
        for (int nt = 0; nt < 8; nt++)
            #pragma unroll
            for (int j = 0; j < 4; j++) s[nt][j] = 0.f;

        #pragma unroll
        for (int k8 = 0; k8 < 8; k8++) {
            uint32_t ah[4], al[4];
            LDSM4(ah[0], ah[1], ah[2], ah[3], aQH + k8 * 32);
            LDSM4(al[0], al[1], al[2], al[3], aQL + k8 * 32);
            #pragma unroll
            for (int np = 0; np < 4; np++) {
                uint32_t bh[4], bl[4];
                LDSM4(bh[0], bh[1], bh[2], bh[3], bKH + np * 4352 + k8 * 32);
                LDSM4(bl[0], bl[1], bl[2], bl[3], bKL + np * 4352 + k8 * 32);
                MMA16816(s[2*np],   ah[0], ah[1], ah[2], ah[3], bh[0], bh[1]);
                MMA16816(s[2*np],   ah[0], ah[1], ah[2], ah[3], bl[0], bl[1]);
                MMA16816(s[2*np],   al[0], al[1], al[2], al[3], bh[0], bh[1]);
                MMA16816(s[2*np+1], ah[0], ah[1], ah[2], ah[3], bh[2], bh[3]);
                MMA16816(s[2*np+1], ah[0], ah[1], ah[2], ah[3], bl[2], bl[3]);
                MMA16816(s[2*np+1], al[0], al[1], al[2], al[3], bh[2], bh[3]);
            }
        }

        // ---- mask + exp2(s - 17.3125) + lsum ----
        const float OFF = 17.3125f;
        const bool nm = (kb + ABN - 1) > (qbase + m0);
        const int r0 = qbase + m0 + g, r1 = r0 + 8;
        #pragma unroll
        for (int nt = 0; nt < 8; nt++) {
            if (nm) {
                int c0 = kb + nt * 8 + q2;
                s[nt][0] = (c0     <= r0) ? ex2f(s[nt][0] - OFF) : 0.f;
                s[nt][1] = (c0 + 1 <= r0) ? ex2f(s[nt][1] - OFF) : 0.f;
                s[nt][2] = (c0     <= r1) ? ex2f(s[nt][2] - OFF) : 0.f;
                s[nt][3] = (c0 + 1 <= r1) ? ex2f(s[nt][3] - OFF) : 0.f;
            } else {
                s[nt][0] = ex2f(s[nt][0] - OFF);
                s[nt][1] = ex2f(s[nt][1] - OFF);
                s[nt][2] = ex2f(s[nt][2] - OFF);
                s[nt][3] = ex2f(s[nt][3] - OFF);
            }
            ls0 += s[nt][0] + s[nt][1];
            ls1 += s[nt][2] + s[nt][3];
        }

        // ---- repack P C-frags -> A-frags (hi/lo) ----
        uint32_t ph[4][4], pl[4][4];
        #pragma unroll
        for (int kk = 0; kk < 4; kk++) {
            int n0 = 2 * kk, n1 = 2 * kk + 1;
            hilo2(s[n0][0], s[n0][1], ph[kk][0], pl[kk][0]);
            hilo2(s[n0][2], s[n0][3], ph[kk][1], pl[kk][1]);
            hilo2(s[n1][0], s[n1][1], ph[kk][2], pl[kk][2]);
            hilo2(s[n1][2], s[n1][3], ph[kk][3], pl[kk][3]);
        }

        // ---- O += P V (V loaded transposed on the fly) ----
        #pragma unroll
        for (int kk = 0; kk < 4; kk++) {
            #pragma unroll
            for (int np = 0; np < 8; np++) {
                uint32_t vh[4], vl[4];
                LDSM4T(vh[0], vh[1], vh[2], vh[3], bVH + kk * 4352 + np * 32);
                LDSM4T(vl[0], vl[1], vl[2], vl[3], bVL + kk * 4352 + np * 32);
                MMA16816(o[2*np],   ph[kk][0], ph[kk][1], ph[kk][2], ph[kk][3], vh[0], vh[1]);
                MMA16816(o[2*np],   ph[kk][0], ph[kk][1], ph[kk][2], ph[kk][3], vl[0], vl[1]);
                MMA16816(o[2*np],   pl[kk][0], pl[kk][1], pl[kk][2], pl[kk][3], vh[0], vh[1]);
                MMA16816(o[2*np+1], ph[kk][0], ph[kk][1], ph[kk][2], ph[kk][3], vh[2], vh[3]);
                MMA16816(o[2*np+1], ph[kk][0], ph[kk][1], ph[kk][2], ph[kk][3], vl[2], vl[3]);
                MMA16816(o[2*np+1], pl[kk][0], pl[kk][1], pl[kk][2], pl[kk][3], vh[2], vh[3]);
            }
        }
    }

    // ---- epilogue: quad-reduce lsum, normalize, store ----
    ls0 += __shfl_xor_sync(0xffffffffu, ls0, 1);
    ls0 += __shfl_xor_sync(0xffffffffu, ls0, 2);
    ls1 += __shfl_xor_sync(0xffffffffu, ls1, 1);
    ls1 += __shfl_xor_sync(0xffffffffu, ls1, 2);
    const float inv0 = 1.0f / ls0, inv1 = 1.0f / ls1;
    float* op = out + ((size_t)b * SEQ + qbase + m0) * DIM;
    #pragma unroll
    for (int nt = 0; nt < 16; nt++) {
        *(float2*)(op + (size_t)g * DIM + nt * 8 + q2) =
            make_float2(o[nt][0] * inv0, o[nt][1] * inv0);
        *(float2*)(op + (size_t)(g + 8) * DIM + nt * 8 + q2) =
            make_float2(o[nt][2] * inv1, o[nt][3] * inv1);
    }
}

// ---------------------------------------------------------------------------
extern "C" void kernel_launch(void* const* d_in, const int* in_sizes, int n_in,
                              void* d_out, int out_size) {
    const float* x  = (const float*)d_in[0];
    const float* Wk = (const float*)d_in[1];
    const float* Wq = (const float*)d_in[2];
    const float* Wv = (const float*)d_in[3];
    float* out = (float*)d_out;

    cudaFuncSetAttribute(qkv_kernel,  cudaFuncAttributeMaxDynamicSharedMemorySize, SMEM_QKV);
    cudaFuncSetAttribute(attn_kernel, cudaFuncAttributeMaxDynamicSharedMemorySize, SMEM_ATTN);

    dim3 qkv_grid(SEQ / QBM, BATCH, 3);
    qkv_kernel<<<qkv_grid, 128, SMEM_QKV>>>(x, Wk, Wq, Wv);

    attn_kernel<<<256, 128, SMEM_ATTN>>>(out);
}

// round 16
// speedup vs baseline: 1.4128x; 1.0279x over previous
#include <cuda_runtime.h>
#include <cuda_bf16.h>
#include <math.h>
#include <cstdint>

#define BATCH 8
#define SEQ   2048
#define DIM   128
#define QBM   64            // qkv token tile
#define ABM   64            // attention q rows per CTA
#define ABN   32            // keys per iteration (double-buffered)
#define NQT   (SEQ / ABM)   // 32

// Attention SMEM byte offsets
// Q hi/lo [64][136]; K,V double-buffered [32][136] hi+lo per buffer
#define SQH 0
#define SQL 17408
#define SKB 34816           // K buf p at SKB + p*17408 (KH +0, KL +8704)
#define SVB 69632           // V buf p at SVB + p*17408 (VH +0, VL +8704)
#define SMEM_ATTN 104448

// QKV SMEM: W hi/lo [128][136], x hi/lo [64][136]
#define SWH 0
#define SWL 34816
#define SXH 69632
#define SXL 87040
#define SMEM_QKV 104448

// Scratch (device globals — no allocation allowed)
__device__ __nv_bfloat16 g_qh[BATCH * SEQ * DIM];
__device__ __nv_bfloat16 g_ql[BATCH * SEQ * DIM];
__device__ __nv_bfloat16 g_kh[BATCH * SEQ * DIM];
__device__ __nv_bfloat16 g_kl[BATCH * SEQ * DIM];
__device__ __nv_bfloat16 g_vh[BATCH * SEQ * DIM];   // natural [b][t][d]
__device__ __nv_bfloat16 g_vl[BATCH * SEQ * DIM];

__device__ __forceinline__ uint32_t smem_u32(const void* p) {
    uint32_t a;
    asm("{ .reg .u64 t; cvta.to.shared.u64 t, %1; cvt.u32.u64 %0, t; }" : "=r"(a) : "l"(p));
    return a;
}
__device__ __forceinline__ float ex2f(float x) {
    float r; asm("ex2.approx.ftz.f32 %0, %1;" : "=f"(r) : "f"(x)); return r;
}

#define LDSM4(r0, r1, r2, r3, addr) \
    asm volatile("ldmatrix.sync.aligned.m8n8.x4.shared.b16 {%0,%1,%2,%3}, [%4];" \
        : "=r"(r0), "=r"(r1), "=r"(r2), "=r"(r3) : "r"(addr))
#define LDSM4T(r0, r1, r2, r3, addr) \
    asm volatile("ldmatrix.sync.aligned.m8n8.x4.trans.shared.b16 {%0,%1,%2,%3}, [%4];" \
        : "=r"(r0), "=r"(r1), "=r"(r2), "=r"(r3) : "r"(addr))
#define MMA16816(c, a0, a1, a2, a3, b0, b1) \
    asm volatile("mma.sync.aligned.m16n8k16.row.col.f32.bf16.bf16.f32 " \
        "{%0,%1,%2,%3}, {%4,%5,%6,%7}, {%8,%9}, {%0,%1,%2,%3};" \
        : "+f"((c)[0]), "+f"((c)[1]), "+f"((c)[2]), "+f"((c)[3]) \
        : "r"(a0), "r"(a1), "r"(a2), "r"(a3), "r"(b0), "r"(b1))
#define CPASYNC16(s, g) \
    asm volatile("cp.async.cg.shared.global [%0], [%1], 16;" :: "r"(s), "l"(g))
#define CPCOMMIT() asm volatile("cp.async.commit_group;" ::: "memory")
#define CPWAIT0()  asm volatile("cp.async.wait_group 0;" ::: "memory")

// split fp32 pair into bf16x2 hi + bf16x2 lo
__device__ __forceinline__ void hilo2(float x, float y, uint32_t& h, uint32_t& l) {
    __nv_bfloat162 hp = __float22bfloat162_rn(make_float2(x, y));
    float2 hf = __bfloat1622float2(hp);
    __nv_bfloat162 lp = __float22bfloat162_rn(make_float2(x - hf.x, y - hf.y));
    h = *(uint32_t*)&hp;
    l = *(uint32_t*)&lp;
}
__device__ __forceinline__ void split4(float4 a, uint2& h, uint2& l) {
    uint32_t h0, l0, h1, l1;
    hilo2(a.x, a.y, h0, l0);
    hilo2(a.z, a.w, h1, l1);
    h.x = h0; h.y = h1; l.x = l0; l.y = l1;
}

// ---------------------------------------------------------------------------
// QKV projection via warp-MMA (3-pass bf16 hi/lo), outputs hi/lo bf16.
// grid (32, 8, 3), 128 threads (4 warps x m16). y[t][d] = sum_c x[t][c] W[d][c]
// ---------------------------------------------------------------------------
__global__ __launch_bounds__(128, 2)
void qkv_kernel(const float* __restrict__ x, const float* __restrict__ Wk,
                const float* __restrict__ Wq, const float* __restrict__ Wv) {
    extern __shared__ char smem[];
    const uint32_t sb = smem_u32(smem);
    const int tid = threadIdx.x, wid = tid >> 5, lane = tid & 31;
    const int tq = blockIdx.x, b = blockIdx.y, which = blockIdx.z;
    const float* W = (which == 0) ? Wq : (which == 1) ? Wk : Wv;

    // W [128][128] f32 -> split hi/lo into smem [128][136]
    #pragma unroll
    for (int j = 0; j < 32; j++) {
        int i = tid + j * 128;
        int r = i >> 5, c4 = (i & 31) * 4;
        float4 w = *(const float4*)(W + r * DIM + c4);
        uint2 h, l; split4(w, h, l);
        *(uint2*)(smem + SWH + r * 272 + c4 * 2) = h;
        *(uint2*)(smem + SWL + r * 272 + c4 * 2) = l;
    }
    // x tile [64][128] f32 (Q pre-scaled) -> split hi/lo
    const float sc = (which == 0) ? (0.08838834764831845f * 1.4426950408889634f) : 1.0f;
    #pragma unroll
    for (int j = 0; j < 16; j++) {
        int i = tid + j * 128;
        int r = i >> 5, c4 = (i & 31) * 4;
        float4 v = *(const float4*)(x + ((size_t)b * SEQ + tq * QBM + r) * DIM + c4);
        v.x *= sc; v.y *= sc; v.z *= sc; v.w *= sc;
        uint2 h, l; split4(v, h, l);
        *(uint2*)(smem + SXH + r * 272 + c4 * 2) = h;
        *(uint2*)(smem + SXL + r * 272 + c4 * 2) = l;
    }
    __syncthreads();

    const int m0 = wid * 16;
    const int g  = lane >> 2, q2 = (lane & 3) * 2;
    const int aRow = m0 + (lane & 7) + ((lane >> 3) & 1) * 8;
    const int aCol = ((lane >> 4) & 1) * 16;
    const uint32_t aXH = sb + SXH + aRow * 272 + aCol;
    const uint32_t aXL = sb + SXL + aRow * 272 + aCol;
    const int bRow4 = (lane & 7) + ((lane >> 4) & 1) * 8;
    const int bCol4 = ((lane >> 3) & 1) * 16;
    const uint32_t bWH = sb + SWH + bRow4 * 272 + bCol4;
    const uint32_t bWL = sb + SWL + bRow4 * 272 + bCol4;

    float c[16][4];
    #pragma unroll
    for (int nt = 0; nt < 16; nt++)
        #pragma unroll
        for (int j = 0; j < 4; j++) c[nt][j] = 0.f;

    #pragma unroll
    for (int k8 = 0; k8 < 8; k8++) {
        uint32_t ah[4], al[4];
        LDSM4(ah[0], ah[1], ah[2], ah[3], aXH + k8 * 32);
        LDSM4(al[0], al[1], al[2], al[3], aXL + k8 * 32);
        #pragma unroll
        for (int np = 0; np < 8; np++) {
            uint32_t bh[4], bl[4];
            LDSM4(bh[0], bh[1], bh[2], bh[3], bWH + np * 4352 + k8 * 32);
            LDSM4(bl[0], bl[1], bl[2], bl[3], bWL + np * 4352 + k8 * 32);
            MMA16816(c[2*np],   ah[0], ah[1], ah[2], ah[3], bh[0], bh[1]);
            MMA16816(c[2*np+1], ah[0], ah[1], ah[2], ah[3], bh[2], bh[3]);
            MMA16816(c[2*np],   ah[0], ah[1], ah[2], ah[3], bl[0], bl[1]);
            MMA16816(c[2*np+1], ah[0], ah[1], ah[2], ah[3], bl[2], bl[3]);
            MMA16816(c[2*np],   al[0], al[1], al[2], al[3], bh[0], bh[1]);
            MMA16816(c[2*np+1], al[0], al[1], al[2], al[3], bh[2], bh[3]);
        }
    }

    __nv_bfloat16* oh = (which == 0) ? g_qh : (which == 1) ? g_kh : g_vh;
    __nv_bfloat16* ol = (which == 0) ? g_ql : (which == 1) ? g_kl : g_vl;
    const size_t r0 = (size_t)b * SEQ + tq * QBM + m0 + g;
    #pragma unroll
    for (int nt = 0; nt < 16; nt++) {
        uint32_t h, l;
        hilo2(c[nt][0], c[nt][1], h, l);
        *(uint32_t*)(oh + r0 * DIM + nt * 8 + q2) = h;
        *(uint32_t*)(ol + r0 * DIM + nt * 8 + q2) = l;
        hilo2(c[nt][2], c[nt][3], h, l);
        *(uint32_t*)(oh + (r0 + 8) * DIM + nt * 8 + q2) = h;
        *(uint32_t*)(ol + (r0 + 8) * DIM + nt * 8 + q2) = l;
    }
}

// ---------------------------------------------------------------------------
// issue cp.async loads for one 32x128 bf16 tile into [32][136] smem
// ---------------------------------------------------------------------------
__device__ __forceinline__ void issue_tile(uint32_t sdst, const __nv_bfloat16* g, int tid) {
    #pragma unroll
    for (int j = 0; j < 4; j++) {
        int i = tid + j * 128;
        int r = i >> 4, c = i & 15;
        CPASYNC16(sdst + r * 272 + c * 16, g + (size_t)r * DIM + c * 8);
    }
}

// ---------------------------------------------------------------------------
// Warp-MMA flash attention, fixed-offset softmax, bf16 2-term x 3 passes.
// 128 threads (4 warps x m16), BM=64, BN=32 double-buffered via cp.async.
// 2 CTAs/SM. Schedule as R15 (singles on SMs 108-147 get mid tiles).
// ---------------------------------------------------------------------------
__global__ __launch_bounds__(128, 2)
void attn_kernel(float* __restrict__ out) {
    extern __shared__ char smem[];
    const uint32_t sb = smem_u32(smem);
    const int tid = threadIdx.x, wid = tid >> 5, lane = tid & 31;

    // ---- work mapping ----
    int qt, b;
    {
        const int bid = blockIdx.x;
        if (bid >= 108 && bid < 148) {                 // singles: mid tiles
            int p = bid - 108;
            qt = 22 + (p >> 3); b = p & 7;
        } else {
            const int i = (bid < 108) ? bid : bid - 148;
            const bool first = (bid < 108);
            if (i < 40)       { qt = first ? 31 - (i >> 3) : (i >> 3);            b = i & 7; }
            else if (i < 104) { int j = i - 40;
                                qt = first ? 21 - (j >> 3) : 5 + (j >> 3);        b = i & 7; }
            else              { int m = i - 104; qt = 13; b = 2 * m + (first ? 0 : 1); }
        }
    }
    const int qbase = qt * ABM;
    const int m0 = wid * 16;
    const int g  = lane >> 2;
    const int q2 = (lane & 3) * 2;
    const int nk = 2 * (qt + 1);           // 32-key tiles

    const __nv_bfloat16* Kh = g_kh + (size_t)b * SEQ * DIM;
    const __nv_bfloat16* Kl = g_kl + (size_t)b * SEQ * DIM;
    const __nv_bfloat16* Vh = g_vh + (size_t)b * SEQ * DIM;
    const __nv_bfloat16* Vl = g_vl + (size_t)b * SEQ * DIM;

    // ---- load Q tile (hi/lo) into SMEM [64][136] ----
    {
        const __nv_bfloat16* qh = g_qh + ((size_t)b * SEQ + qbase) * DIM;
        const __nv_bfloat16* ql = g_ql + ((size_t)b * SEQ + qbase) * DIM;
        #pragma unroll
        for (int j = 0; j < 8; j++) {
            int i = tid + j * 128;
            int r = i >> 4, cs = i & 15;
            CPASYNC16(sb + SQH + r * 272 + cs * 16, qh + (size_t)r * DIM + cs * 8);
            CPASYNC16(sb + SQL + r * 272 + cs * 16, ql + (size_t)r * DIM + cs * 8);
        }
    }
    // ---- prologue: issue K(0), V(0) into buffer 0 ----
    issue_tile(sb + SKB,        Kh, tid);
    issue_tile(sb + SKB + 8704, Kl, tid);
    issue_tile(sb + SVB,        Vh, tid);
    issue_tile(sb + SVB + 8704, Vl, tid);
    CPCOMMIT();

    // ldmatrix per-lane base addresses
    const int aRow = m0 + (lane & 7) + ((lane >> 3) & 1) * 8;
    const int aCol = ((lane >> 4) & 1) * 16;
    const uint32_t aQH = sb + SQH + aRow * 272 + aCol;
    const uint32_t aQL = sb + SQL + aRow * 272 + aCol;
    const int bRow4 = (lane & 7) + ((lane >> 4) & 1) * 8;
    const int bCol4 = ((lane >> 3) & 1) * 16;
    const uint32_t bKoff = bRow4 * 272 + bCol4;          // + SKB + p*17408 (+8704 lo)
    const int vRow = (lane & 7) + ((lane >> 3) & 1) * 8;
    const int vCol = ((lane >> 4) & 1) * 16;
    const uint32_t bVoff = vRow * 272 + vCol;            // + SVB + p*17408 (+8704 lo)

    float o[16][4];
    #pragma unroll
    for (int nt = 0; nt < 16; nt++)
        #pragma unroll
        for (int j = 0; j < 4; j++) o[nt][j] = 0.f;
    float ls0 = 0.f, ls1 = 0.f;

    for (int kt = 0; kt < nk; kt++) {
        const int kb = kt * ABN;
        const uint32_t pb = (uint32_t)(kt & 1) * 17408;

        CPWAIT0();
        __syncthreads();   // buf[p] data visible; everyone done reading buf[1-p]

        if (kt + 1 < nk) {  // prefetch next tile into the other buffer
            const uint32_t qb2 = (uint32_t)((kt + 1) & 1) * 17408;
            const size_t kb2 = (size_t)(kt + 1) * ABN * DIM;
            issue_tile(sb + SKB + qb2,        Kh + kb2, tid);
            issue_tile(sb + SKB + qb2 + 8704, Kl + kb2, tid);
            issue_tile(sb + SVB + qb2,        Vh + kb2, tid);
            issue_tile(sb + SVB + qb2 + 8704, Vl + kb2, tid);
            CPCOMMIT();
        }

        // ---- S = Q K^T (np 0..1, accumulators interleaved) ----
        float s[4][4];
        #pragma unroll
        for (int nt = 0; nt < 4; nt++)
            #pragma unroll
            for (int j = 0; j < 4; j++) s[nt][j] = 0.f;

        const uint32_t bKH = sb + SKB + pb + bKoff;
        const uint32_t bKL = bKH + 8704;
        #pragma unroll
        for (int k8 = 0; k8 < 8; k8++) {
            uint32_t ah[4], al[4];
            LDSM4(ah[0], ah[1], ah[2], ah[3], aQH + k8 * 32);
            LDSM4(al[0], al[1], al[2], al[3], aQL + k8 * 32);
            #pragma unroll
            for (int np = 0; np < 2; np++) {
                uint32_t bh[4], bl[4];
                LDSM4(bh[0], bh[1], bh[2], bh[3], bKH + np * 4352 + k8 * 32);
                LDSM4(bl[0], bl[1], bl[2], bl[3], bKL + np * 4352 + k8 * 32);
                MMA16816(s[2*np],   ah[0], ah[1], ah[2], ah[3], bh[0], bh[1]);
                MMA16816(s[2*np+1], ah[0], ah[1], ah[2], ah[3], bh[2], bh[3]);
                MMA16816(s[2*np],   ah[0], ah[1], ah[2], ah[3], bl[0], bl[1]);
                MMA16816(s[2*np+1], ah[0], ah[1], ah[2], ah[3], bl[2], bl[3]);
                MMA16816(s[2*np],   al[0], al[1], al[2], al[3], bh[0], bh[1]);
                MMA16816(s[2*np+1], al[0], al[1], al[2], al[3], bh[2], bh[3]);
            }
        }

        // ---- mask + exp2(s - 17.3125) + lsum ----
        const float OFF = 17.3125f;
        const bool nm = (kb + ABN - 1) > (qbase + m0);
        const int r0 = qbase + m0 + g, r1 = r0 + 8;
        #pragma unroll
        for (int nt = 0; nt < 4; nt++) {
            if (nm) {
                int c0 = kb + nt * 8 + q2;
                s[nt][0] = (c0     <= r0) ? ex2f(s[nt][0] - OFF) : 0.f;
                s[nt][1] = (c0 + 1 <= r0) ? ex2f(s[nt][1] - OFF) : 0.f;
                s[nt][2] = (c0     <= r1) ? ex2f(s[nt][2] - OFF) : 0.f;
                s[nt][3] = (c0 + 1 <= r1) ? ex2f(s[nt][3] - OFF) : 0.f;
            } else {
                s[nt][0] = ex2f(s[nt][0] - OFF);
                s[nt][1] = ex2f(s[nt][1] - OFF);
                s[nt][2] = ex2f(s[nt][2] - OFF);
                s[nt][3] = ex2f(s[nt][3] - OFF);
            }
            ls0 += s[nt][0] + s[nt][1];
            ls1 += s[nt][2] + s[nt][3];
        }

        // ---- repack P C-frags -> A-frags (hi/lo) ----
        uint32_t ph[2][4], pl[2][4];
        #pragma unroll
        for (int kk = 0; kk < 2; kk++) {
            int n0 = 2 * kk, n1 = 2 * kk + 1;
            hilo2(s[n0][0], s[n0][1], ph[kk][0], pl[kk][0]);
            hilo2(s[n0][2], s[n0][3], ph[kk][1], pl[kk][1]);
            hilo2(s[n1][0], s[n1][1], ph[kk][2], pl[kk][2]);
            hilo2(s[n1][2], s[n1][3], ph[kk][3], pl[kk][3]);
        }

        // ---- O += P V (V loaded transposed on the fly) ----
        const uint32_t bVH = sb + SVB + pb + bVoff;
        const uint32_t bVL = bVH + 8704;
        #pragma unroll
        for (int kk = 0; kk < 2; kk++) {
            #pragma unroll
            for (int np = 0; np < 8; np++) {
                uint32_t vh[4], vl[4];
                LDSM4T(vh[0], vh[1], vh[2], vh[3], bVH + kk * 4352 + np * 32);
                LDSM4T(vl[0], vl[1], vl[2], vl[3], bVL + kk * 4352 + np * 32);
                MMA16816(o[2*np],   ph[kk][0], ph[kk][1], ph[kk][2], ph[kk][3], vh[0], vh[1]);
                MMA16816(o[2*np+1], ph[kk][0], ph[kk][1], ph[kk][2], ph[kk][3], vh[2], vh[3]);
                MMA16816(o[2*np],   ph[kk][0], ph[kk][1], ph[kk][2], ph[kk][3], vl[0], vl[1]);
                MMA16816(o[2*np+1], ph[kk][0], ph[kk][1], ph[kk][2], ph[kk][3], vl[2], vl[3]);
                MMA16816(o[2*np],   pl[kk][0], pl[kk][1], pl[kk][2], pl[kk][3], vh[0], vh[1]);
                MMA16816(o[2*np+1], pl[kk][0], pl[kk][1], pl[kk][2], pl[kk][3], vh[2], vh[3]);
            }
        }
    }

    // ---- epilogue: quad-reduce lsum, normalize, store ----
    ls0 += __shfl_xor_sync(0xffffffffu, ls0, 1);
    ls0 += __shfl_xor_sync(0xffffffffu, ls0, 2);
    ls1 += __shfl_xor_sync(0xffffffffu, ls1, 1);
    ls1 += __shfl_xor_sync(0xffffffffu, ls1, 2);
    const float inv0 = 1.0f / ls0, inv1 = 1.0f / ls1;
    float* op = out + ((size_t)b * SEQ + qbase + m0) * DIM;
    #pragma unroll
    for (int nt = 0; nt < 16; nt++) {
        *(float2*)(op + (size_t)g * DIM + nt * 8 + q2) =
            make_float2(o[nt][0] * inv0, o[nt][1] * inv0);
        *(float2*)(op + (size_t)(g + 8) * DIM + nt * 8 + q2) =
            make_float2(o[nt][2] * inv1, o[nt][3] * inv1);
    }
}

// ---------------------------------------------------------------------------
extern "C" void kernel_launch(void* const* d_in, const int* in_sizes, int n_in,
                              void* d_out, int out_size) {
    const float* x  = (const float*)d_in[0];
    const float* Wk = (const float*)d_in[1];
    const float* Wq = (const float*)d_in[2];
    const float* Wv = (const float*)d_in[3];
    float* out = (float*)d_out;

    cudaFuncSetAttribute(qkv_kernel,  cudaFuncAttributeMaxDynamicSharedMemorySize, SMEM_QKV);
    cudaFuncSetAttribute(attn_kernel, cudaFuncAttributeMaxDynamicSharedMemorySize, SMEM_ATTN);

    dim3 qkv_grid(SEQ / QBM, BATCH, 3);
    qkv_kernel<<<qkv_grid, 128, SMEM_QKV>>>(x, Wk, Wq, Wv);

    attn_kernel<<<256, 128, SMEM_ATTN>>>(out);
}